// round 8
// baseline (speedup 1.0000x reference)
#include <cuda_runtime.h>
#include <cuda_fp16.h>
#include <math.h>
#include <stdint.h>

#define BB   64
#define SS   2048
#define EH   512
#define AH   512

#define SPLITS 32
#define SCH    (SS / SPLITS)    // 64

// scratch (no allocations allowed)
__device__ float g_dec_proj[BB * AH];
__device__ float g_score[BB * SS];
__device__ float g_ctx_part[SPLITS * BB * EH];

// ---------------------------------------------------------------------------
__device__ __forceinline__ float fast_tanh(float x) {
    float y; asm("tanh.approx.f32 %0, %1;" : "=f"(y) : "f"(x)); return y;
}
__device__ __forceinline__ uint32_t smem_u32(const void* p) {
    uint32_t a;
    asm("{ .reg .u64 t; cvta.to.shared.u64 t, %1; cvt.u32.u64 %0, t; }"
        : "=r"(a) : "l"(p));
    return a;
}
__device__ __forceinline__ uint32_t ph2(float lo, float hi) {
    __half2 h = __floats2half2_rn(lo, hi);   // .x = lo (low 16 bits)
    return *(uint32_t*)&h;
}
__device__ __forceinline__ void ldsm_x4(uint32_t* r, uint32_t addr) {
    asm volatile("ldmatrix.sync.aligned.m8n8.x4.shared.b16 {%0,%1,%2,%3}, [%4];"
                 : "=r"(r[0]), "=r"(r[1]), "=r"(r[2]), "=r"(r[3]) : "r"(addr));
}
__device__ __forceinline__ void ldsm_x2(uint32_t* r, uint32_t addr) {
    asm volatile("ldmatrix.sync.aligned.m8n8.x2.shared.b16 {%0,%1}, [%2];"
                 : "=r"(r[0]), "=r"(r[1]) : "r"(addr));
}
__device__ __forceinline__ void mma_fp16(float* c, const uint32_t* a, const uint32_t* b) {
    asm volatile(
        "mma.sync.aligned.m16n8k16.row.col.f32.f16.f16.f32 "
        "{%0,%1,%2,%3}, {%4,%5,%6,%7}, {%8,%9}, {%0,%1,%2,%3};\n"
        : "+f"(c[0]), "+f"(c[1]), "+f"(c[2]), "+f"(c[3])
        : "r"(a[0]), "r"(a[1]), "r"(a[2]), "r"(a[3]),
          "r"(b[0]), "r"(b[1]));
}

// ---------------------------------------------------------------------------
// K1: dec_proj[b,a] = sum_d dec_hidden[b,d] * W_dec[a,d]
// ---------------------------------------------------------------------------
__global__ void dec_proj_kernel(const float* __restrict__ dec_hidden,
                                const float* __restrict__ W_dec) {
    int b = blockIdx.x;
    __shared__ float sh[EH];
    for (int i = threadIdx.x; i < EH; i += blockDim.x)
        sh[i] = dec_hidden[b * EH + i];
    __syncthreads();

    int warp = threadIdx.x >> 5;
    int lane = threadIdx.x & 31;
    int nwarp = blockDim.x >> 5;
    for (int a = warp; a < AH; a += nwarp) {
        const float* wr = W_dec + (size_t)a * EH;
        float acc = 0.f;
        #pragma unroll 4
        for (int d = lane; d < EH; d += 32)
            acc += sh[d] * wr[d];
        #pragma unroll
        for (int o = 16; o > 0; o >>= 1)
            acc += __shfl_xor_sync(0xffffffffu, acc, o);
        if (lane == 0) g_dec_proj[b * AH + a] = acc;
    }
}

// ---------------------------------------------------------------------------
// K2: fused score kernel, fp16 mma.sync m16n8k16 + ldmatrix.
//   score[b,s] = sum_a tanh(enc_proj[b,s,a] + dec_proj[b,a]) * v[a]
// CTA tile 128(s) x 128(a) x KT=32; 8 warps = 2(m) x 4(n), warp 64x32.
// Smem tiles row-major fp16, row stride 40 halfs (80B) -> ldmatrix and
// STS.128 writer both conflict-free.  Epilogue identical to tf32 version
// (C fragment layout is the same).
// ---------------------------------------------------------------------------
#define KT     32
#define NKCH   (EH / KT)   // 16
#define RSTRW  20          // row stride in 32-bit words (40 halfs = 80B)

__global__ void __launch_bounds__(256, 1) score_kernel(
        const float* __restrict__ enc,
        const float* __restrict__ Wenc,
        const float* __restrict__ v) {
    const int b  = blockIdx.y;
    const int s0 = blockIdx.x * 128;
    const int tid = threadIdx.x;
    const int wid = tid >> 5;
    const int lane = tid & 31;
    const int g = lane >> 2;
    const int t = lane & 3;
    const int warp_m = (wid & 1) * 64;
    const int warp_n = (wid >> 1) * 32;
    const int wn_idx = wid >> 1;

    __shared__ uint32_t As[128 * RSTRW];
    __shared__ uint32_t Bs[128 * RSTRW];
    __shared__ float sv[128];
    __shared__ float sdec[128];
    __shared__ float sscore[128];
    __shared__ float red[128 * 4];

    const uint32_t as_base = smem_u32(As);
    const uint32_t bs_base = smem_u32(Bs);

    const float* encb = enc + ((size_t)b * SS + s0) * EH;

    // writer slot: kbw in {0,1} selects k16 half, rr = row (A) / col (B)
    const int kbw = tid >> 7;
    const int rr  = tid & 127;

    // ldmatrix per-lane address components (byte offsets)
    const int lq = lane & 15;          // A: row within 16
    const int lh = lane >> 4;          // A: k-half select (+16B)
    const int bq = lane & 7;           // B: col within 8
    const int bh = (lane >> 3) & 1;    // B: k-half select (+16B)

    if (tid < 128) sscore[tid] = 0.f;

    for (int a0 = 0; a0 < AH; a0 += 128) {
        const float* wb = Wenc + (size_t)a0 * EH;

        if (tid < 128) {
            sv[tid]   = v[a0 + tid];
            sdec[tid] = g_dec_proj[b * AH + a0 + tid];
        }

        float acc[4][4][4];
        #pragma unroll
        for (int mf = 0; mf < 4; mf++)
            #pragma unroll
            for (int nf = 0; nf < 4; nf++)
                #pragma unroll
                for (int cc = 0; cc < 4; cc++) acc[mf][nf][cc] = 0.f;

        const float* aptr = encb + (size_t)rr * EH + kbw * 16;
        const float* bptr = wb   + (size_t)rr * EH + kbw * 16;

        // ---- prologue: chunk 0 -> regs -> smem ----
        float4 ra[4], rb[4];
        #pragma unroll
        for (int j = 0; j < 4; j++) {
            ra[j] = *(const float4*)(aptr + j * 4);
            rb[j] = *(const float4*)(bptr + j * 4);
        }
        __syncthreads();   // previous a-iter's smem reads complete
        {
            uint4 w0 = make_uint4(ph2(ra[0].x, ra[0].y), ph2(ra[0].z, ra[0].w),
                                  ph2(ra[1].x, ra[1].y), ph2(ra[1].z, ra[1].w));
            uint4 w1 = make_uint4(ph2(ra[2].x, ra[2].y), ph2(ra[2].z, ra[2].w),
                                  ph2(ra[3].x, ra[3].y), ph2(ra[3].z, ra[3].w));
            *(uint4*)&As[rr * RSTRW + kbw * 8]     = w0;
            *(uint4*)&As[rr * RSTRW + kbw * 8 + 4] = w1;
            uint4 v0 = make_uint4(ph2(rb[0].x, rb[0].y), ph2(rb[0].z, rb[0].w),
                                  ph2(rb[1].x, rb[1].y), ph2(rb[1].z, rb[1].w));
            uint4 v1 = make_uint4(ph2(rb[2].x, rb[2].y), ph2(rb[2].z, rb[2].w),
                                  ph2(rb[3].x, rb[3].y), ph2(rb[3].z, rb[3].w));
            *(uint4*)&Bs[rr * RSTRW + kbw * 8]     = v0;
            *(uint4*)&Bs[rr * RSTRW + kbw * 8 + 4] = v1;
        }
        __syncthreads();

        // ---- main K loop ----
        for (int chunk = 0; chunk < NKCH; chunk++) {
            if (chunk + 1 < NKCH) {
                int k0 = (chunk + 1) * KT;
                #pragma unroll
                for (int j = 0; j < 4; j++) {
                    ra[j] = *(const float4*)(aptr + k0 + j * 4);
                    rb[j] = *(const float4*)(bptr + k0 + j * 4);
                }
            }

            #pragma unroll
            for (int kb = 0; kb < 2; kb++) {
                uint32_t af[4][4];
                #pragma unroll
                for (int mf = 0; mf < 4; mf++) {
                    uint32_t addr = as_base
                        + ((warp_m + mf * 16 + lq) * RSTRW + kb * 8) * 4
                        + lh * 16;
                    ldsm_x4(af[mf], addr);
                }
                uint32_t bf[4][2];
                #pragma unroll
                for (int nf = 0; nf < 4; nf++) {
                    uint32_t addr = bs_base
                        + ((warp_n + nf * 8 + bq) * RSTRW + kb * 8) * 4
                        + bh * 16;
                    ldsm_x2(bf[nf], addr);
                }
                #pragma unroll
                for (int mf = 0; mf < 4; mf++)
                    #pragma unroll
                    for (int nf = 0; nf < 4; nf++)
                        mma_fp16(acc[mf][nf], af[mf], bf[nf]);
            }

            if (chunk + 1 < NKCH) {
                __syncthreads();
                uint4 w0 = make_uint4(ph2(ra[0].x, ra[0].y), ph2(ra[0].z, ra[0].w),
                                      ph2(ra[1].x, ra[1].y), ph2(ra[1].z, ra[1].w));
                uint4 w1 = make_uint4(ph2(ra[2].x, ra[2].y), ph2(ra[2].z, ra[2].w),
                                      ph2(ra[3].x, ra[3].y), ph2(ra[3].z, ra[3].w));
                *(uint4*)&As[rr * RSTRW + kbw * 8]     = w0;
                *(uint4*)&As[rr * RSTRW + kbw * 8 + 4] = w1;
                uint4 v0 = make_uint4(ph2(rb[0].x, rb[0].y), ph2(rb[0].z, rb[0].w),
                                      ph2(rb[1].x, rb[1].y), ph2(rb[1].z, rb[1].w));
                uint4 v1 = make_uint4(ph2(rb[2].x, rb[2].y), ph2(rb[2].z, rb[2].w),
                                      ph2(rb[3].x, rb[3].y), ph2(rb[3].z, rb[3].w));
                *(uint4*)&Bs[rr * RSTRW + kbw * 8]     = v0;
                *(uint4*)&Bs[rr * RSTRW + kbw * 8 + 4] = v1;
                __syncthreads();
            }
        }

        // ---- epilogue: tanh(acc + dec) * v, reduce over the 128 a-cols ----
        float rowsum[4][2];
        #pragma unroll
        for (int mf = 0; mf < 4; mf++) { rowsum[mf][0] = 0.f; rowsum[mf][1] = 0.f; }

        #pragma unroll
        for (int mf = 0; mf < 4; mf++) {
            #pragma unroll
            for (int nf = 0; nf < 4; nf++) {
                int nbase = warp_n + nf * 8 + t * 2;
                #pragma unroll
                for (int cc = 0; cc < 4; cc++) {
                    int n = nbase + (cc & 1);
                    float x = acc[mf][nf][cc] + sdec[n];
                    rowsum[mf][cc >> 1] += fast_tanh(x) * sv[n];
                }
            }
        }
        #pragma unroll
        for (int mf = 0; mf < 4; mf++) {
            #pragma unroll
            for (int o = 0; o < 2; o++) {
                rowsum[mf][o] += __shfl_xor_sync(0xffffffffu, rowsum[mf][o], 1);
                rowsum[mf][o] += __shfl_xor_sync(0xffffffffu, rowsum[mf][o], 2);
            }
        }
        if (t == 0) {
            #pragma unroll
            for (int mf = 0; mf < 4; mf++) {
                red[(warp_m + mf * 16 + g)     * 4 + wn_idx] = rowsum[mf][0];
                red[(warp_m + mf * 16 + g + 8) * 4 + wn_idx] = rowsum[mf][1];
            }
        }
        __syncthreads();
        if (tid < 128) {
            float4 rrv = *(const float4*)&red[tid * 4];
            sscore[tid] += (rrv.x + rrv.y) + (rrv.z + rrv.w);
        }
        __syncthreads();
    }

    if (tid < 128)
        g_score[b * SS + s0 + tid] = sscore[tid];
}

// ---------------------------------------------------------------------------
// K3: softmax over S per batch row. weights -> d_out + B*EH
// ---------------------------------------------------------------------------
__global__ void __launch_bounds__(256) softmax_kernel(float* __restrict__ out_w) {
    const int b   = blockIdx.x;
    const int tid = threadIdx.x;
    __shared__ float sred[32];

    float vals[8];
    float vmax = -1e30f;
    #pragma unroll
    for (int i = 0; i < 8; i++) {
        vals[i] = g_score[b * SS + tid + i * 256];
        vmax = fmaxf(vmax, vals[i]);
    }
    #pragma unroll
    for (int o = 16; o > 0; o >>= 1)
        vmax = fmaxf(vmax, __shfl_xor_sync(0xffffffffu, vmax, o));
    if ((tid & 31) == 0) sred[tid >> 5] = vmax;
    __syncthreads();
    float bmax = sred[0];
    #pragma unroll
    for (int w = 1; w < 8; w++) bmax = fmaxf(bmax, sred[w]);

    float vsum = 0.f;
    #pragma unroll
    for (int i = 0; i < 8; i++) {
        vals[i] = expf(vals[i] - bmax);
        vsum += vals[i];
    }
    #pragma unroll
    for (int o = 16; o > 0; o >>= 1)
        vsum += __shfl_xor_sync(0xffffffffu, vsum, o);
    __syncthreads();
    if ((tid & 31) == 0) sred[tid >> 5] = vsum;
    __syncthreads();
    float bsum = 0.f;
    #pragma unroll
    for (int w = 0; w < 8; w++) bsum += sred[w];

    float inv = __frcp_rn(bsum);
    #pragma unroll
    for (int i = 0; i < 8; i++)
        out_w[b * SS + tid + i * 256] = vals[i] * inv;
}

// ---------------------------------------------------------------------------
// K4a: partial context over an S-chunk
// ---------------------------------------------------------------------------
__global__ void __launch_bounds__(128) context_partial_kernel(
        const float* __restrict__ enc,
        const float* __restrict__ w) {
    const int b  = blockIdx.x;
    const int sp = blockIdx.y;
    const int e4 = threadIdx.x << 2;

    const float* wb   = w + b * SS + sp * SCH;
    const float* encb = enc + ((size_t)b * SS + (size_t)sp * SCH) * EH + e4;

    float4 acc = make_float4(0.f, 0.f, 0.f, 0.f);
    #pragma unroll 4
    for (int s = 0; s < SCH; s++) {
        float ws = wb[s];
        float4 ev = *(const float4*)(encb + (size_t)s * EH);
        acc.x += ws * ev.x;
        acc.y += ws * ev.y;
        acc.z += ws * ev.z;
        acc.w += ws * ev.w;
    }
    *(float4*)&g_ctx_part[((size_t)sp * BB + b) * EH + e4] = acc;
}

// ---------------------------------------------------------------------------
// K4b: deterministic reduce of the SPLITS partials into ctx (d_out)
// ---------------------------------------------------------------------------
__global__ void __launch_bounds__(256) context_reduce_kernel(float* __restrict__ ctx) {
    const int i = blockIdx.x * 256 + threadIdx.x;
    float s = 0.f;
    #pragma unroll
    for (int sp = 0; sp < SPLITS; sp++)
        s += g_ctx_part[(size_t)sp * BB * EH + i];
    ctx[i] = s;
}

// ---------------------------------------------------------------------------
extern "C" void kernel_launch(void* const* d_in, const int* in_sizes, int n_in,
                              void* d_out, int out_size) {
    const float* enc   = (const float*)d_in[0];  // [B,S,EH]
    const float* dec   = (const float*)d_in[1];  // [B,EH]
    const float* W_enc = (const float*)d_in[2];  // [AH,EH]
    const float* W_dec = (const float*)d_in[3];  // [AH,EH]
    const float* v     = (const float*)d_in[4];  // [1,AH]

    float* out = (float*)d_out;
    float* out_ctx = out;                 // [B, EH]
    float* out_w   = out + BB * EH;       // [B, S]

    dec_proj_kernel<<<BB, 256>>>(dec, W_dec);

    dim3 g2(SS / 128, BB);
    score_kernel<<<g2, 256>>>(enc, W_enc, v);

    softmax_kernel<<<BB, 256>>>(out_w);

    dim3 g4(BB, SPLITS);
    context_partial_kernel<<<g4, 128>>>(enc, out_w);

    context_reduce_kernel<<<(BB * EH) / 256, 256>>>(out_ctx);
}

// round 9
// speedup vs baseline: 1.2714x; 1.2714x over previous
#include <cuda_runtime.h>
#include <math.h>
#include <stdint.h>

#define BB   64
#define SS   2048
#define EH   512
#define AH   512

#define SPLITS 32
#define SCH    (SS / SPLITS)    // 64

// scratch (no allocations allowed)
__device__ float g_dec_proj[BB * AH];
__device__ float g_score[BB * SS];
__device__ float g_ctx_part[SPLITS * BB * EH];

// ---------------------------------------------------------------------------
__device__ __forceinline__ uint32_t f2tf32(float x) {
    uint32_t r;
    asm("cvt.rna.tf32.f32 %0, %1;" : "=r"(r) : "f"(x));
    return r;
}
__device__ __forceinline__ float fast_tanh(float x) {
    float y; asm("tanh.approx.f32 %0, %1;" : "=f"(y) : "f"(x)); return y;
}
__device__ __forceinline__ void mma_tf32(float* c, const uint32_t* a, const uint32_t* b) {
    asm volatile(
        "mma.sync.aligned.m16n8k8.row.col.f32.tf32.tf32.f32 "
        "{%0,%1,%2,%3}, {%4,%5,%6,%7}, {%8,%9}, {%0,%1,%2,%3};\n"
        : "+f"(c[0]), "+f"(c[1]), "+f"(c[2]), "+f"(c[3])
        : "r"(a[0]), "r"(a[1]), "r"(a[2]), "r"(a[3]),
          "r"(b[0]), "r"(b[1]));
}

// ---------------------------------------------------------------------------
// K1: dec_proj[b,a] = sum_d dec_hidden[b,d] * W_dec[a,d]
// ---------------------------------------------------------------------------
__global__ void dec_proj_kernel(const float* __restrict__ dec_hidden,
                                const float* __restrict__ W_dec) {
    int b = blockIdx.x;
    __shared__ float sh[EH];
    for (int i = threadIdx.x; i < EH; i += blockDim.x)
        sh[i] = dec_hidden[b * EH + i];
    __syncthreads();

    int warp = threadIdx.x >> 5;
    int lane = threadIdx.x & 31;
    int nwarp = blockDim.x >> 5;
    for (int a = warp; a < AH; a += nwarp) {
        const float* wr = W_dec + (size_t)a * EH;
        float acc = 0.f;
        #pragma unroll 4
        for (int d = lane; d < EH; d += 32)
            acc += sh[d] * wr[d];
        #pragma unroll
        for (int o = 16; o > 0; o >>= 1)
            acc += __shfl_xor_sync(0xffffffffu, acc, o);
        if (lane == 0) g_dec_proj[b * AH + a] = acc;
    }
}

// ---------------------------------------------------------------------------
// K2: fused score kernel (tf32 mma.sync m16n8k8), frag-major smem layout,
//     DOUBLE-BUFFERED tiles (1 barrier per K-chunk), occupancy 2.
//   score[b,s] = sum_a tanh(enc_proj[b,s,a] + dec_proj[b,a]) * v[a]
// CTA tile 128(s) x 128(a) x KT=32 chunks; 8 warps = 2(m) x 4(n), warp 64x32.
// ---------------------------------------------------------------------------
#define KT     32
#define NKCH   (EH / KT)   // 16
#define AW_PAD 1028        // words per A kb-tile (1024 + 4 pad, 16B aligned)
#define BW_PAD 1026        // words per B kb-tile (1024 + 2 pad, 8B aligned)
#define AWORDS (4 * AW_PAD)   // 4112
#define BWORDS (4 * BW_PAD)   // 4104
// dynamic smem word offsets
#define OFF_AS0  0
#define OFF_BS0  (OFF_AS0 + AWORDS)              // 4112
#define OFF_AS1  (OFF_BS0 + BWORDS)              // 8216
#define OFF_BS1  (OFF_AS1 + AWORDS)              // 12328
#define OFF_SV   (OFF_BS1 + BWORDS)              // 16432
#define OFF_SDEC (OFF_SV + 128)
#define OFF_SSC  (OFF_SDEC + 128)
#define OFF_RED  (OFF_SSC + 128)
#define SMEM_WORDS (OFF_RED + 512)               // 17328
#define SMEM_BYTES (SMEM_WORDS * 4)              // 69312

// store one thread's share of a KT chunk (regs -> frag-major smem tiles)
__device__ __forceinline__ void store_tiles(uint32_t* __restrict__ Ab,
                                            uint32_t* __restrict__ Bb,
                                            const float4* ra, const float4* rb,
                                            int tid) {
    #pragma unroll
    for (int j = 0; j < 4; j++) {
        int i = tid + j * 256;
        int m = i >> 3, k4 = i & 7;
        int kb = k4 >> 1, khigh = k4 & 1;
        {
            int mb = m >> 4, gg = m & 7, rh = (m >> 3) & 1;
            int base = kb * AW_PAD + mb * 128 + khigh * 2 + rh;
            const float* f = &ra[j].x;
            #pragma unroll
            for (int c = 0; c < 4; c++)
                Ab[base + (gg * 4 + c) * 4] = f2tf32(f[c]);
        }
        {
            int nb = m >> 3, gg = m & 7;
            int base = kb * BW_PAD + nb * 64 + khigh;
            const float* f = &rb[j].x;
            #pragma unroll
            for (int c = 0; c < 4; c++)
                Bb[base + (gg * 4 + c) * 2] = f2tf32(f[c]);
        }
    }
}

__global__ void __launch_bounds__(256, 2) score_kernel(
        const float* __restrict__ enc,
        const float* __restrict__ Wenc,
        const float* __restrict__ v) {
    extern __shared__ uint32_t dsm[];
    const int b  = blockIdx.y;
    const int s0 = blockIdx.x * 128;
    const int tid = threadIdx.x;
    const int wid = tid >> 5;
    const int lane = tid & 31;
    const int g = lane >> 2;
    const int t = lane & 3;
    const int warp_m = (wid & 1) * 64;
    const int warp_n = (wid >> 1) * 32;
    const int wn_idx = wid >> 1;

    uint32_t* const Abuf[2] = {dsm + OFF_AS0, dsm + OFF_AS1};
    uint32_t* const Bbuf[2] = {dsm + OFF_BS0, dsm + OFF_BS1};
    float* sv     = (float*)(dsm + OFF_SV);
    float* sdec   = (float*)(dsm + OFF_SDEC);
    float* sscore = (float*)(dsm + OFF_SSC);
    float* red    = (float*)(dsm + OFF_RED);

    const float* encb = enc + ((size_t)b * SS + s0) * EH;

    if (tid < 128) sscore[tid] = 0.f;

    for (int a0 = 0; a0 < AH; a0 += 128) {
        const float* wb = Wenc + (size_t)a0 * EH;

        if (tid < 128) {
            sv[tid]   = v[a0 + tid];
            sdec[tid] = g_dec_proj[b * AH + a0 + tid];
        }

        float acc[4][4][4];
        #pragma unroll
        for (int mf = 0; mf < 4; mf++)
            #pragma unroll
            for (int nf = 0; nf < 4; nf++)
                #pragma unroll
                for (int cc = 0; cc < 4; cc++) acc[mf][nf][cc] = 0.f;

        // ---- prologue: chunk 0 -> regs -> buf0 ----
        float4 ra[4], rb[4];
        #pragma unroll
        for (int j = 0; j < 4; j++) {
            int i = tid + j * 256;
            int m = i >> 3, k4 = i & 7;
            ra[j] = *(const float4*)&encb[(size_t)m * EH + k4 * 4];
            rb[j] = *(const float4*)&wb  [(size_t)m * EH + k4 * 4];
        }
        store_tiles(Abuf[0], Bbuf[0], ra, rb, tid);
        __syncthreads();

        // ---- main K loop: 1 barrier per chunk (double buffer) ----
        for (int chunk = 0; chunk < NKCH; chunk++) {
            const uint32_t* As = Abuf[chunk & 1];
            const uint32_t* Bs = Bbuf[chunk & 1];

            if (chunk + 1 < NKCH) {
                int k0 = (chunk + 1) * KT;
                #pragma unroll
                for (int j = 0; j < 4; j++) {
                    int i = tid + j * 256;
                    int m = i >> 3, k4 = i & 7;
                    ra[j] = *(const float4*)&encb[(size_t)m * EH + k0 + k4 * 4];
                    rb[j] = *(const float4*)&wb  [(size_t)m * EH + k0 + k4 * 4];
                }
            }

            #pragma unroll
            for (int kb = 0; kb < 4; kb++) {
                uint4 af[4];
                #pragma unroll
                for (int mf = 0; mf < 4; mf++) {
                    int mb = (wid & 1) * 4 + mf;
                    af[mf] = *(const uint4*)&As[kb * AW_PAD + mb * 128 + lane * 4];
                }
                uint2 bf[4];
                #pragma unroll
                for (int nf = 0; nf < 4; nf++) {
                    int nb = (wid >> 1) * 4 + nf;
                    bf[nf] = *(const uint2*)&Bs[kb * BW_PAD + nb * 64 + lane * 2];
                }
                #pragma unroll
                for (int mf = 0; mf < 4; mf++)
                    #pragma unroll
                    for (int nf = 0; nf < 4; nf++)
                        mma_tf32(acc[mf][nf], (const uint32_t*)&af[mf],
                                 (const uint32_t*)&bf[nf]);
            }

            if (chunk + 1 < NKCH)
                store_tiles(Abuf[(chunk + 1) & 1], Bbuf[(chunk + 1) & 1],
                            ra, rb, tid);
            __syncthreads();
        }

        // ---- epilogue: tanh(acc + dec) * v, reduce over the 128 a-cols ----
        float rowsum[4][2];
        #pragma unroll
        for (int mf = 0; mf < 4; mf++) { rowsum[mf][0] = 0.f; rowsum[mf][1] = 0.f; }

        #pragma unroll
        for (int mf = 0; mf < 4; mf++) {
            #pragma unroll
            for (int nf = 0; nf < 4; nf++) {
                int nbase = warp_n + nf * 8 + t * 2;
                #pragma unroll
                for (int cc = 0; cc < 4; cc++) {
                    int n = nbase + (cc & 1);
                    float x = acc[mf][nf][cc] + sdec[n];
                    rowsum[mf][cc >> 1] += fast_tanh(x) * sv[n];
                }
            }
        }
        #pragma unroll
        for (int mf = 0; mf < 4; mf++) {
            #pragma unroll
            for (int o = 0; o < 2; o++) {
                rowsum[mf][o] += __shfl_xor_sync(0xffffffffu, rowsum[mf][o], 1);
                rowsum[mf][o] += __shfl_xor_sync(0xffffffffu, rowsum[mf][o], 2);
            }
        }
        if (t == 0) {
            #pragma unroll
            for (int mf = 0; mf < 4; mf++) {
                red[(warp_m + mf * 16 + g)     * 4 + wn_idx] = rowsum[mf][0];
                red[(warp_m + mf * 16 + g + 8) * 4 + wn_idx] = rowsum[mf][1];
            }
        }
        __syncthreads();
        if (tid < 128) {
            float4 rr = *(const float4*)&red[tid * 4];
            sscore[tid] += (rr.x + rr.y) + (rr.z + rr.w);
        }
        __syncthreads();
    }

    if (tid < 128)
        g_score[b * SS + s0 + tid] = sscore[tid];
}

// ---------------------------------------------------------------------------
// K3: softmax over S per batch row. weights -> d_out + B*EH
// ---------------------------------------------------------------------------
__global__ void __launch_bounds__(256) softmax_kernel(float* __restrict__ out_w) {
    const int b   = blockIdx.x;
    const int tid = threadIdx.x;
    __shared__ float sred[32];

    float vals[8];
    float vmax = -1e30f;
    #pragma unroll
    for (int i = 0; i < 8; i++) {
        vals[i] = g_score[b * SS + tid + i * 256];
        vmax = fmaxf(vmax, vals[i]);
    }
    #pragma unroll
    for (int o = 16; o > 0; o >>= 1)
        vmax = fmaxf(vmax, __shfl_xor_sync(0xffffffffu, vmax, o));
    if ((tid & 31) == 0) sred[tid >> 5] = vmax;
    __syncthreads();
    float bmax = sred[0];
    #pragma unroll
    for (int w = 1; w < 8; w++) bmax = fmaxf(bmax, sred[w]);

    float vsum = 0.f;
    #pragma unroll
    for (int i = 0; i < 8; i++) {
        vals[i] = expf(vals[i] - bmax);
        vsum += vals[i];
    }
    #pragma unroll
    for (int o = 16; o > 0; o >>= 1)
        vsum += __shfl_xor_sync(0xffffffffu, vsum, o);
    __syncthreads();
    if ((tid & 31) == 0) sred[tid >> 5] = vsum;
    __syncthreads();
    float bsum = 0.f;
    #pragma unroll
    for (int w = 0; w < 8; w++) bsum += sred[w];

    float inv = __frcp_rn(bsum);
    #pragma unroll
    for (int i = 0; i < 8; i++)
        out_w[b * SS + tid + i * 256] = vals[i] * inv;
}

// ---------------------------------------------------------------------------
// K4a: partial context over an S-chunk
// ---------------------------------------------------------------------------
__global__ void __launch_bounds__(128) context_partial_kernel(
        const float* __restrict__ enc,
        const float* __restrict__ w) {
    const int b  = blockIdx.x;
    const int sp = blockIdx.y;
    const int e4 = threadIdx.x << 2;

    const float* wb   = w + b * SS + sp * SCH;
    const float* encb = enc + ((size_t)b * SS + (size_t)sp * SCH) * EH + e4;

    float4 acc = make_float4(0.f, 0.f, 0.f, 0.f);
    #pragma unroll 4
    for (int s = 0; s < SCH; s++) {
        float ws = wb[s];
        float4 ev = *(const float4*)(encb + (size_t)s * EH);
        acc.x += ws * ev.x;
        acc.y += ws * ev.y;
        acc.z += ws * ev.z;
        acc.w += ws * ev.w;
    }
    *(float4*)&g_ctx_part[((size_t)sp * BB + b) * EH + e4] = acc;
}

// ---------------------------------------------------------------------------
// K4b: deterministic reduce of the SPLITS partials into ctx (d_out)
// ---------------------------------------------------------------------------
__global__ void __launch_bounds__(256) context_reduce_kernel(float* __restrict__ ctx) {
    const int i = blockIdx.x * 256 + threadIdx.x;
    float s = 0.f;
    #pragma unroll
    for (int sp = 0; sp < SPLITS; sp++)
        s += g_ctx_part[(size_t)sp * BB * EH + i];
    ctx[i] = s;
}

// ---------------------------------------------------------------------------
extern "C" void kernel_launch(void* const* d_in, const int* in_sizes, int n_in,
                              void* d_out, int out_size) {
    const float* enc   = (const float*)d_in[0];  // [B,S,EH]
    const float* dec   = (const float*)d_in[1];  // [B,EH]
    const float* W_enc = (const float*)d_in[2];  // [AH,EH]
    const float* W_dec = (const float*)d_in[3];  // [AH,EH]
    const float* v     = (const float*)d_in[4];  // [1,AH]

    float* out = (float*)d_out;
    float* out_ctx = out;                 // [B, EH]
    float* out_w   = out + BB * EH;       // [B, S]

    static int smem_set = 0;
    if (!smem_set) {
        cudaFuncSetAttribute(score_kernel,
                             cudaFuncAttributeMaxDynamicSharedMemorySize,
                             SMEM_BYTES);
        smem_set = 1;
    }

    dec_proj_kernel<<<BB, 256>>>(dec, W_dec);

    dim3 g2(SS / 128, BB);
    score_kernel<<<g2, 256, SMEM_BYTES>>>(enc, W_enc, v);

    softmax_kernel<<<BB, 256>>>(out_w);

    dim3 g4(BB, SPLITS);
    context_partial_kernel<<<g4, 128>>>(enc, out_w);

    context_reduce_kernel<<<(BB * EH) / 256, 256>>>(out_ctx);
}